// round 14
// baseline (speedup 1.0000x reference)
#include <cuda_runtime.h>

// Problem constants
#define Sv   4096
#define Nv   262144
#define Ev   128
#define Hv   8
#define Dv   16
#define CKVv 64
#define QKD  512      // Hv * CKVv
#define XP   68       // padded row stride (floats) for 64-wide rows -> conflict-free
#define WQP  132      // padded row stride for 128-wide rows (Wq)

// Device scratch (invariants for graph replay: g_cnt zero, g_done zero at entry;
// the last pre block restores both after consuming).
__device__ __align__(16) float g_Wv[Ev * CKVv];   // folded V weights [128][64]
__device__ __align__(16) float g_qk[Sv * QKD];    // per-segment folded query [S][8][64]
__device__ __align__(16) int g_cnt[Sv];
__device__ __align__(16) int g_offs[Sv + 4];
__device__ __align__(16) int g_cursor[Sv];
__device__ int g_order[Nv];
__device__ unsigned g_done;

// ---------------------------------------------------------------------------
// pre_kernel (launch 0): histogram + Q/qk precompute + Wv fold + LAST-BLOCK SCAN.
// WARP-PER-SEGMENT: 512 blocks x 8 warps. Padded smem rows (132/68) are
// conflict-free in both access orientations.
// ---------------------------------------------------------------------------
__global__ void __launch_bounds__(256)
pre_kernel(const float* __restrict__ sp, const float* __restrict__ Wq,
           const float* __restrict__ Wkv, const int* __restrict__ assign) {
    extern __shared__ float dyn[];
    float* Wq_s = dyn;                     // [128][WQP]
    float* Wk_s = dyn + Ev * WQP;          // [128][XP] folded K
    __shared__ float strip[8][2 * Ev];     // per warp: sp row | Q
    __shared__ int warp_tot[8];
    __shared__ bool isLast;

    int t = threadIdx.x, lane = t & 31, wid = t >> 5;

    // histogram (grid-stride)
    for (int p = blockIdx.x * 256 + t; p < Nv; p += 512 * 256)
        atomicAdd(&g_cnt[assign[p]], 1);

    // stage Wq (padded)
    for (int idx = t; idx < Ev * Ev / 4; idx += 256) {
        int j = idx >> 5, i4 = idx & 31;
        float4 v = ((const float4*)Wq)[idx];
        *(float4*)&Wq_s[j * WQP + (i4 << 2)] = v;
    }
    // fold + stage Wk (concat-duplication: cols c and c+64 summed)
    for (int idx = t; idx < Ev * CKVv / 4; idx += 256) {
        int r = idx >> 4, c4 = idx & 15;
        float4 a = *(const float4*)&Wkv[(size_t)r * 128 + c4 * 4];
        float4 b = *(const float4*)&Wkv[(size_t)r * 128 + 64 + c4 * 4];
        *(float4*)&Wk_s[r * XP + (c4 << 2)] =
            make_float4(a.x + b.x, a.y + b.y, a.z + b.z, a.w + b.w);
    }
    // block 0: fold Wv to global
    if (blockIdx.x == 0) {
        for (int idx = t; idx < Ev * CKVv / 4; idx += 256) {
            int r = idx >> 4, c4 = idx & 15;
            float4 a = *(const float4*)&Wkv[(size_t)(128 + r) * 128 + c4 * 4];
            float4 b = *(const float4*)&Wkv[(size_t)(128 + r) * 128 + 64 + c4 * 4];
            ((float4*)g_Wv)[idx] = make_float4(a.x + b.x, a.y + b.y, a.z + b.z, a.w + b.w);
        }
    }
    __syncthreads();

    int s = blockIdx.x * 8 + wid;
    float* sps = strip[wid];
    float* Qs  = strip[wid] + Ev;

    ((float4*)sps)[lane] = ((const float4*)(sp + (size_t)s * Ev))[lane];
    __syncwarp();

    // Q: lane owns j in {lane, lane+32, lane+64, lane+96}
    #pragma unroll
    for (int k = 0; k < 4; ++k) {
        int j = lane + 32 * k;
        const float* wr = Wq_s + (size_t)j * WQP;
        float acc = 0.f;
        #pragma unroll
        for (int i4 = 0; i4 < 32; ++i4) {
            float4 w = *(const float4*)&wr[i4 << 2];
            acc = fmaf(w.x, sps[i4 * 4 + 0], acc);
            acc = fmaf(w.y, sps[i4 * 4 + 1], acc);
            acc = fmaf(w.z, sps[i4 * 4 + 2], acc);
            acc = fmaf(w.w, sps[i4 * 4 + 3], acc);
        }
        Qs[j] = acc;
    }
    __syncwarp();

    // qk: lane (g, c4) owns heads {g, g+2, g+4, g+6}
    int g = lane >> 4, c4 = lane & 15;
    #pragma unroll
    for (int hh = 0; hh < 4; ++hh) {
        int h = g + 2 * hh;
        float4 a = make_float4(0.f, 0.f, 0.f, 0.f);
        #pragma unroll
        for (int d = 0; d < Dv; ++d) {
            int r = h * Dv + d;
            float q = Qs[r];
            float4 w = *(const float4*)&Wk_s[r * XP + (c4 << 2)];
            a.x = fmaf(q, w.x, a.x);
            a.y = fmaf(q, w.y, a.y);
            a.z = fmaf(q, w.z, a.z);
            a.w = fmaf(q, w.w, a.w);
        }
        a.x *= 0.25f; a.y *= 0.25f; a.z *= 0.25f; a.w *= 0.25f;
        *(float4*)&g_qk[(size_t)s * QKD + h * CKVv + c4 * 4] = a;
    }

    // ---- last-block-done scan of the histogram ----
    __syncthreads();
    if (t == 0) {
        __threadfence();
        unsigned v = atomicAdd(&g_done, 1u);
        isLast = (v == 511u);
    }
    __syncthreads();
    if (!isLast) return;

    // 256 threads scan 4096 bins: each thread owns 16 consecutive bins.
    int arr[16];
    {
        const int4* cp = (const int4*)g_cnt + t * 4;
        int4 c0 = cp[0], c1 = cp[1], c2 = cp[2], c3 = cp[3];
        arr[0]=c0.x; arr[1]=c0.y; arr[2]=c0.z; arr[3]=c0.w;
        arr[4]=c1.x; arr[5]=c1.y; arr[6]=c1.z; arr[7]=c1.w;
        arr[8]=c2.x; arr[9]=c2.y; arr[10]=c2.z; arr[11]=c2.w;
        arr[12]=c3.x; arr[13]=c3.y; arr[14]=c3.z; arr[15]=c3.w;
    }
    int tot = 0;
    #pragma unroll
    for (int j = 0; j < 16; ++j) tot += arr[j];
    int v = tot;
    #pragma unroll
    for (int o = 1; o < 32; o <<= 1) {
        int u = __shfl_up_sync(0xffffffffu, v, o);
        if (lane >= o) v += u;
    }
    if (lane == 31) warp_tot[wid] = v;
    __syncthreads();
    if (wid == 0) {
        int wv = (lane < 8) ? warp_tot[lane] : 0;
        #pragma unroll
        for (int o = 1; o < 8; o <<= 1) {
            int u = __shfl_up_sync(0xffffffffu, wv, o);
            if (lane >= o) wv += u;
        }
        if (lane < 8) warp_tot[lane] = wv;   // inclusive warp totals
    }
    __syncthreads();
    int excl = (wid ? warp_tot[wid - 1] : 0) + (v - tot);
    #pragma unroll
    for (int j = 0; j < 16; ++j) {
        int bin = t * 16 + j;
        g_offs[bin]   = excl;
        g_cursor[bin] = excl;
        excl += arr[j];
    }
    if (t == 255) g_offs[Sv] = excl;
    // reset invariants for next graph replay
    {
        int4 z = make_int4(0, 0, 0, 0);
        int4* cp = (int4*)g_cnt + t * 4;
        cp[0] = z; cp[1] = z; cp[2] = z; cp[3] = z;
    }
    if (t == 0) g_done = 0u;
}

// ---------------------------------------------------------------------------
// scatter_kernel (launch 1)
// ---------------------------------------------------------------------------
__global__ void scatter_kernel(const int* __restrict__ assign) {
    int tid = blockIdx.x * blockDim.x + threadIdx.x;
    if (tid < Nv) {
        int s = assign[tid];
        int pos = atomicAdd(&g_cursor[s], 1);
        g_order[pos] = tid;
    }
}

// ---------------------------------------------------------------------------
// seg_kernel (launch 2 — PROFILED): warp-autonomous core + FUSED Wv/LN tail.
// One block per segment, chunk = 128 points, padded-68 x tile.
// ---------------------------------------------------------------------------
__global__ void __launch_bounds__(128, 5)
seg_kernel(const float* __restrict__ xin, const float* __restrict__ sp,
           const float* __restrict__ lnw, const float* __restrict__ lnb,
           float* __restrict__ out, float* __restrict__ attn_out) {
    __shared__ float x_s[128 * XP];       // 34816 B; reused: reduction buf, then Wv
    __shared__ float qk_s[QKD];
    __shared__ float w_s[4 * Hv * 32];
    __shared__ float den_red[4 * Hv];
    __shared__ float A_s[Hv * CKVv];
    __shared__ float den_s[Hv];
    __shared__ float red_s[4];

    int s = blockIdx.x, t = threadIdx.x;
    int wi = t >> 5, lane = t & 31;
    int g = lane >> 4, c4 = lane & 15;

    ((float4*)qk_s)[t] = ((const float4*)(g_qk + (size_t)s * QKD))[t];

    int start = g_offs[s], end = g_offs[s + 1];
    float4 A0 = make_float4(0.f,0.f,0.f,0.f), A1 = A0, A2 = A0, A3 = A0;
    float d0 = 0.f, d1 = 0.f, d2 = 0.f, d3 = 0.f;
    __syncthreads();

    for (int base = start; base < end; base += 128) {
        int P = min(128, end - base);

        for (int idx = t; idx < P * 16; idx += 128) {
            int r = idx >> 4, cc = idx & 15;
            int p = g_order[base + r];
            float4 v = ((const float4*)xin)[(size_t)p * 16 + cc];
            *(float4*)&x_s[r * XP + (cc << 2)] = v;
        }
        __syncthreads();

        // ---- score phase (warp-local) ----
        int r = wi * 32 + lane;
        if (r < P) {
            const float* xrow = x_s + r * XP;
            float sc0=0.f,sc1=0.f,sc2=0.f,sc3=0.f,sc4=0.f,sc5=0.f,sc6=0.f,sc7=0.f;
            #pragma unroll
            for (int i = 0; i < 16; ++i) {
                float4 x = *(const float4*)&xrow[i << 2];
                float4 q;
                q = *(const float4*)&qk_s[0 * 64 + (i << 2)];
                sc0 = fmaf(q.x,x.x,sc0); sc0 = fmaf(q.y,x.y,sc0);
                sc0 = fmaf(q.z,x.z,sc0); sc0 = fmaf(q.w,x.w,sc0);
                q = *(const float4*)&qk_s[1 * 64 + (i << 2)];
                sc1 = fmaf(q.x,x.x,sc1); sc1 = fmaf(q.y,x.y,sc1);
                sc1 = fmaf(q.z,x.z,sc1); sc1 = fmaf(q.w,x.w,sc1);
                q = *(const float4*)&qk_s[2 * 64 + (i << 2)];
                sc2 = fmaf(q.x,x.x,sc2); sc2 = fmaf(q.y,x.y,sc2);
                sc2 = fmaf(q.z,x.z,sc2); sc2 = fmaf(q.w,x.w,sc2);
                q = *(const float4*)&qk_s[3 * 64 + (i << 2)];
                sc3 = fmaf(q.x,x.x,sc3); sc3 = fmaf(q.y,x.y,sc3);
                sc3 = fmaf(q.z,x.z,sc3); sc3 = fmaf(q.w,x.w,sc3);
                q = *(const float4*)&qk_s[4 * 64 + (i << 2)];
                sc4 = fmaf(q.x,x.x,sc4); sc4 = fmaf(q.y,x.y,sc4);
                sc4 = fmaf(q.z,x.z,sc4); sc4 = fmaf(q.w,x.w,sc4);
                q = *(const float4*)&qk_s[5 * 64 + (i << 2)];
                sc5 = fmaf(q.x,x.x,sc5); sc5 = fmaf(q.y,x.y,sc5);
                sc5 = fmaf(q.z,x.z,sc5); sc5 = fmaf(q.w,x.w,sc5);
                q = *(const float4*)&qk_s[6 * 64 + (i << 2)];
                sc6 = fmaf(q.x,x.x,sc6); sc6 = fmaf(q.y,x.y,sc6);
                sc6 = fmaf(q.z,x.z,sc6); sc6 = fmaf(q.w,x.w,sc6);
                q = *(const float4*)&qk_s[7 * 64 + (i << 2)];
                sc7 = fmaf(q.x,x.x,sc7); sc7 = fmaf(q.y,x.y,sc7);
                sc7 = fmaf(q.z,x.z,sc7); sc7 = fmaf(q.w,x.w,sc7);
            }
            float* wb = w_s + wi * (Hv * 32);
            wb[0 * 32 + lane] = __expf(sc0);
            wb[1 * 32 + lane] = __expf(sc1);
            wb[2 * 32 + lane] = __expf(sc2);
            wb[3 * 32 + lane] = __expf(sc3);
            wb[4 * 32 + lane] = __expf(sc4);
            wb[5 * 32 + lane] = __expf(sc5);
            wb[6 * 32 + lane] = __expf(sc6);
            wb[7 * 32 + lane] = __expf(sc7);
            float ssum = sc0+sc1+sc2+sc3+sc4+sc5+sc6+sc7;
            attn_out[g_order[base + r]] = ssum * 0.125f;
        }
        __syncwarp();

        // ---- update phase (warp-local) ----
        int r0 = wi * 32;
        int Pw = P - r0;
        if (Pw > 32) Pw = 32;
        if (Pw > 0) {
            const float* wb = w_s + wi * (Hv * 32);
            int Pm = Pw & ~3;
            for (int pb = 0; pb < Pm; pb += 4) {
                float4 x0 = *(const float4*)&x_s[(r0 + pb + 0) * XP + (c4 << 2)];
                float4 x1 = *(const float4*)&x_s[(r0 + pb + 1) * XP + (c4 << 2)];
                float4 x2 = *(const float4*)&x_s[(r0 + pb + 2) * XP + (c4 << 2)];
                float4 x3 = *(const float4*)&x_s[(r0 + pb + 3) * XP + (c4 << 2)];
                float4 w4;
                w4 = *(const float4*)&wb[(g + 0) * 32 + pb];
                A0.x = fmaf(w4.x,x0.x,A0.x); A0.y = fmaf(w4.x,x0.y,A0.y);
                A0.z = fmaf(w4.x,x0.z,A0.z); A0.w = fmaf(w4.x,x0.w,A0.w);
                A0.x = fmaf(w4.y,x1.x,A0.x); A0.y = fmaf(w4.y,x1.y,A0.y);
                A0.z = fmaf(w4.y,x1.z,A0.z); A0.w = fmaf(w4.y,x1.w,A0.w);
                A0.x = fmaf(w4.z,x2.x,A0.x); A0.y = fmaf(w4.z,x2.y,A0.y);
                A0.z = fmaf(w4.z,x2.z,A0.z); A0.w = fmaf(w4.z,x2.w,A0.w);
                A0.x = fmaf(w4.w,x3.x,A0.x); A0.y = fmaf(w4.w,x3.y,A0.y);
                A0.z = fmaf(w4.w,x3.z,A0.z); A0.w = fmaf(w4.w,x3.w,A0.w);
                d0 += w4.x + w4.y + w4.z + w4.w;
                w4 = *(const float4*)&wb[(g + 2) * 32 + pb];
                A1.x = fmaf(w4.x,x0.x,A1.x); A1.y = fmaf(w4.x,x0.y,A1.y);
                A1.z = fmaf(w4.x,x0.z,A1.z); A1.w = fmaf(w4.x,x0.w,A1.w);
                A1.x = fmaf(w4.y,x1.x,A1.x); A1.y = fmaf(w4.y,x1.y,A1.y);
                A1.z = fmaf(w4.y,x1.z,A1.z); A1.w = fmaf(w4.y,x1.w,A1.w);
                A1.x = fmaf(w4.z,x2.x,A1.x); A1.y = fmaf(w4.z,x2.y,A1.y);
                A1.z = fmaf(w4.z,x2.z,A1.z); A1.w = fmaf(w4.z,x2.w,A1.w);
                A1.x = fmaf(w4.w,x3.x,A1.x); A1.y = fmaf(w4.w,x3.y,A1.y);
                A1.z = fmaf(w4.w,x3.z,A1.z); A1.w = fmaf(w4.w,x3.w,A1.w);
                d1 += w4.x + w4.y + w4.z + w4.w;
                w4 = *(const float4*)&wb[(g + 4) * 32 + pb];
                A2.x = fmaf(w4.x,x0.x,A2.x); A2.y = fmaf(w4.x,x0.y,A2.y);
                A2.z = fmaf(w4.x,x0.z,A2.z); A2.w = fmaf(w4.x,x0.w,A2.w);
                A2.x = fmaf(w4.y,x1.x,A2.x); A2.y = fmaf(w4.y,x1.y,A2.y);
                A2.z = fmaf(w4.y,x1.z,A2.z); A2.w = fmaf(w4.y,x1.w,A2.w);
                A2.x = fmaf(w4.z,x2.x,A2.x); A2.y = fmaf(w4.z,x2.y,A2.y);
                A2.z = fmaf(w4.z,x2.z,A2.z); A2.w = fmaf(w4.z,x2.w,A2.w);
                A2.x = fmaf(w4.w,x3.x,A2.x); A2.y = fmaf(w4.w,x3.y,A2.y);
                A2.z = fmaf(w4.w,x3.z,A2.z); A2.w = fmaf(w4.w,x3.w,A2.w);
                d2 += w4.x + w4.y + w4.z + w4.w;
                w4 = *(const float4*)&wb[(g + 6) * 32 + pb];
                A3.x = fmaf(w4.x,x0.x,A3.x); A3.y = fmaf(w4.x,x0.y,A3.y);
                A3.z = fmaf(w4.x,x0.z,A3.z); A3.w = fmaf(w4.x,x0.w,A3.w);
                A3.x = fmaf(w4.y,x1.x,A3.x); A3.y = fmaf(w4.y,x1.y,A3.y);
                A3.z = fmaf(w4.y,x1.z,A3.z); A3.w = fmaf(w4.y,x1.w,A3.w);
                A3.x = fmaf(w4.z,x2.x,A3.x); A3.y = fmaf(w4.z,x2.y,A3.y);
                A3.z = fmaf(w4.z,x2.z,A3.z); A3.w = fmaf(w4.z,x2.w,A3.w);
                A3.x = fmaf(w4.w,x3.x,A3.x); A3.y = fmaf(w4.w,x3.y,A3.y);
                A3.z = fmaf(w4.w,x3.z,A3.z); A3.w = fmaf(w4.w,x3.w,A3.w);
                d3 += w4.x + w4.y + w4.z + w4.w;
            }
            for (int k = Pm; k < Pw; ++k) {
                float4 xv = *(const float4*)&x_s[(r0 + k) * XP + (c4 << 2)];
                float w0 = wb[(g + 0) * 32 + k];
                float w1 = wb[(g + 2) * 32 + k];
                float w2 = wb[(g + 4) * 32 + k];
                float w3 = wb[(g + 6) * 32 + k];
                A0.x = fmaf(w0,xv.x,A0.x); A0.y = fmaf(w0,xv.y,A0.y);
                A0.z = fmaf(w0,xv.z,A0.z); A0.w = fmaf(w0,xv.w,A0.w);
                A1.x = fmaf(w1,xv.x,A1.x); A1.y = fmaf(w1,xv.y,A1.y);
                A1.z = fmaf(w1,xv.z,A1.z); A1.w = fmaf(w1,xv.w,A1.w);
                A2.x = fmaf(w2,xv.x,A2.x); A2.y = fmaf(w2,xv.y,A2.y);
                A2.z = fmaf(w2,xv.z,A2.z); A2.w = fmaf(w2,xv.w,A2.w);
                A3.x = fmaf(w3,xv.x,A3.x); A3.y = fmaf(w3,xv.y,A3.y);
                A3.z = fmaf(w3,xv.z,A3.z); A3.w = fmaf(w3,xv.w,A3.w);
                d0 += w0; d1 += w1; d2 += w2; d3 += w3;
            }
        }
        __syncthreads();
    }

    // ---- 4-warp reduction (x_s reused as [4][8][64] buffer) ----
    {
        float* rb = x_s + wi * QKD;
        *(float4*)&rb[(g + 0) * 64 + c4 * 4] = A0;
        *(float4*)&rb[(g + 2) * 64 + c4 * 4] = A1;
        *(float4*)&rb[(g + 4) * 64 + c4 * 4] = A2;
        *(float4*)&rb[(g + 6) * 64 + c4 * 4] = A3;
        if (c4 == 0) {
            den_red[wi * Hv + g + 0] = d0;
            den_red[wi * Hv + g + 2] = d1;
            den_red[wi * Hv + g + 4] = d2;
            den_red[wi * Hv + g + 6] = d3;
        }
    }
    __syncthreads();

    {
        int h = t >> 4, c4t = t & 15;
        float4 a0 = *(const float4*)&x_s[0 * QKD + h * 64 + c4t * 4];
        float4 a1 = *(const float4*)&x_s[1 * QKD + h * 64 + c4t * 4];
        float4 a2 = *(const float4*)&x_s[2 * QKD + h * 64 + c4t * 4];
        float4 a3 = *(const float4*)&x_s[3 * QKD + h * 64 + c4t * 4];
        *(float4*)&A_s[h * CKVv + c4t * 4] =
            make_float4(a0.x + a1.x + a2.x + a3.x,
                        a0.y + a1.y + a2.y + a3.y,
                        a0.z + a1.z + a2.z + a3.z,
                        a0.w + a1.w + a2.w + a3.w);
        if (c4t == 0)
            den_s[h] = den_red[0 * Hv + h] + den_red[1 * Hv + h] +
                       den_red[2 * Hv + h] + den_red[3 * Hv + h];
    }
    __syncthreads();

    // ---- fused tail: stage Wv into x_s (overwrite), ctx + residual + LN ----
    for (int idx = t; idx < Ev * CKVv / 4; idx += 128) {
        int r = idx >> 4, cc = idx & 15;
        float4 v = ((const float4*)g_Wv)[idx];
        *(float4*)&x_s[r * XP + (cc << 2)] = v;
    }
    __syncthreads();

    {
        int h = t >> 4;
        const float* wr = x_s + (size_t)t * XP;
        const float* ah = A_s + h * CKVv;
        float acc = 0.f;
        #pragma unroll
        for (int i = 0; i < 16; ++i) {
            float4 w = *(const float4*)&wr[i << 2];
            const float* a = ah + (i << 2);
            acc = fmaf(w.x, a[0], acc);
            acc = fmaf(w.y, a[1], acc);
            acc = fmaf(w.z, a[2], acc);
            acc = fmaf(w.w, a[3], acc);
        }
        float dd  = den_s[h];
        float ctx = dd > 0.f ? acc / dd : 0.f;
        float xval = sp[(size_t)s * Ev + t] + ctx;

        float v = xval;
        #pragma unroll
        for (int o = 16; o; o >>= 1) v += __shfl_xor_sync(0xffffffffu, v, o);
        if (lane == 0) red_s[wi] = v;
        __syncthreads();
        float mu = (red_s[0] + red_s[1] + red_s[2] + red_s[3]) * (1.f / Ev);
        float dv = xval - mu;
        float sq = dv * dv;
        #pragma unroll
        for (int o = 16; o; o >>= 1) sq += __shfl_xor_sync(0xffffffffu, sq, o);
        __syncthreads();
        if (lane == 0) red_s[wi] = sq;
        __syncthreads();
        float rstd = rsqrtf((red_s[0] + red_s[1] + red_s[2] + red_s[3]) * (1.f / Ev) + 1e-5f);
        out[(size_t)s * Ev + t] = dv * rstd * lnw[t] + lnb[t];
    }
}

// ---------------------------------------------------------------------------
// Launch: 3 launches (pre, scatter, seg).
// ---------------------------------------------------------------------------
extern "C" void kernel_launch(void* const* d_in, const int* in_sizes, int n_in,
                              void* d_out, int out_size) {
    const float* sp     = (const float*)d_in[0];
    const float* xin    = (const float*)d_in[1];
    const int*   assign = (const int*)d_in[2];
    const float* Wq     = (const float*)d_in[3];
    const float* Wkv    = (const float*)d_in[4];
    const float* lnw    = (const float*)d_in[5];
    const float* lnb    = (const float*)d_in[6];
    float* out      = (float*)d_out;
    float* attn_out = out + (size_t)Sv * Ev;

    int pre_smem = (Ev * WQP + Ev * XP) * (int)sizeof(float);    // 102.4 KB dynamic
    cudaFuncSetAttribute(pre_kernel, cudaFuncAttributeMaxDynamicSharedMemorySize, pre_smem);
    pre_kernel<<<512, 256, pre_smem>>>(sp, Wq, Wkv, assign);

    scatter_kernel<<<Nv / 256, 256>>>(assign);
    seg_kernel<<<Sv, 128>>>(xin, sp, lnw, lnb, out, attn_out);
}

// round 15
// speedup vs baseline: 1.1014x; 1.1014x over previous
#include <cuda_runtime.h>

// Problem constants
#define Sv   4096
#define Nv   262144
#define Ev   128
#define Hv   8
#define Dv   16
#define CKVv 64
#define QKD  512      // Hv * CKVv
#define XP   68       // padded row stride (floats) for 64-wide rows -> conflict-free
#define WQP  132      // padded row stride for 128-wide rows (Wq)
#define PREB 296      // pre grid (2 blocks/SM)

// Device scratch (g_cnt invariant: zero at kernel_launch entry; scan re-zeroes)
__device__ __align__(16) float g_Wv[Ev * CKVv];   // folded V weights [128][64]
__device__ __align__(16) float g_qk[Sv * QKD];    // per-segment folded query [S][8][64]
__device__ __align__(16) int g_cnt[Sv];
__device__ __align__(16) int g_offs[Sv + 4];
__device__ __align__(16) int g_cursor[Sv];
__device__ int g_order[Nv];

// ---------------------------------------------------------------------------
// pre_kernel (launch 0): histogram + Q/qk precompute + Wv fold.
// 296 blocks x 8 warps; warps LOOP segments (stride 2368) with no in-loop
// block barriers. Padded smem rows (132/68) are conflict-free both ways.
// launch_bounds(256,2): regs capped at 128 -> 2 blocks/SM (smem-matched).
// ---------------------------------------------------------------------------
__global__ void __launch_bounds__(256, 2)
pre_kernel(const float* __restrict__ sp, const float* __restrict__ Wq,
           const float* __restrict__ Wkv, const int* __restrict__ assign) {
    extern __shared__ float dyn[];
    float* Wq_s = dyn;                     // [128][WQP]
    float* Wk_s = dyn + Ev * WQP;          // [128][XP] folded K
    __shared__ float strip[8][2 * Ev];     // per warp: sp row | Q

    int t = threadIdx.x, lane = t & 31, wid = t >> 5;

    // histogram (grid-stride over all points)
    for (int p = blockIdx.x * 256 + t; p < Nv; p += PREB * 256)
        atomicAdd(&g_cnt[assign[p]], 1);

    // stage Wq (padded)
    for (int idx = t; idx < Ev * Ev / 4; idx += 256) {
        int j = idx >> 5, i4 = idx & 31;
        float4 v = ((const float4*)Wq)[idx];
        *(float4*)&Wq_s[j * WQP + (i4 << 2)] = v;
    }
    // fold + stage Wk (concat-duplication: cols c and c+64 summed)
    for (int idx = t; idx < Ev * CKVv / 4; idx += 256) {
        int r = idx >> 4, c4 = idx & 15;
        float4 a = *(const float4*)&Wkv[(size_t)r * 128 + c4 * 4];
        float4 b = *(const float4*)&Wkv[(size_t)r * 128 + 64 + c4 * 4];
        *(float4*)&Wk_s[r * XP + (c4 << 2)] =
            make_float4(a.x + b.x, a.y + b.y, a.z + b.z, a.w + b.w);
    }
    // block 0: fold Wv to global
    if (blockIdx.x == 0) {
        for (int idx = t; idx < Ev * CKVv / 4; idx += 256) {
            int r = idx >> 4, c4 = idx & 15;
            float4 a = *(const float4*)&Wkv[(size_t)(128 + r) * 128 + c4 * 4];
            float4 b = *(const float4*)&Wkv[(size_t)(128 + r) * 128 + 64 + c4 * 4];
            ((float4*)g_Wv)[idx] = make_float4(a.x + b.x, a.y + b.y, a.z + b.z, a.w + b.w);
        }
    }
    __syncthreads();   // the only block barrier

    float* sps = strip[wid];
    float* Qs  = strip[wid] + Ev;
    int g = lane >> 4, c4 = lane & 15;

    for (int s = blockIdx.x * 8 + wid; s < Sv; s += PREB * 8) {
        ((float4*)sps)[lane] = ((const float4*)(sp + (size_t)s * Ev))[lane];
        __syncwarp();

        // Q: lane owns j in {lane, lane+32, lane+64, lane+96} — 4 indep chains
        #pragma unroll
        for (int k = 0; k < 4; ++k) {
            int j = lane + 32 * k;
            const float* wr = Wq_s + (size_t)j * WQP;
            float acc = 0.f;
            #pragma unroll
            for (int i4 = 0; i4 < 32; ++i4) {
                float4 w = *(const float4*)&wr[i4 << 2];
                acc = fmaf(w.x, sps[i4 * 4 + 0], acc);
                acc = fmaf(w.y, sps[i4 * 4 + 1], acc);
                acc = fmaf(w.z, sps[i4 * 4 + 2], acc);
                acc = fmaf(w.w, sps[i4 * 4 + 3], acc);
            }
            Qs[j] = acc;
        }
        __syncwarp();

        // qk: lane (g, c4) owns heads {g, g+2, g+4, g+6}
        #pragma unroll
        for (int hh = 0; hh < 4; ++hh) {
            int h = g + 2 * hh;
            float4 a = make_float4(0.f, 0.f, 0.f, 0.f);
            #pragma unroll
            for (int d = 0; d < Dv; ++d) {
                int r = h * Dv + d;
                float q = Qs[r];
                float4 w = *(const float4*)&Wk_s[r * XP + (c4 << 2)];
                a.x = fmaf(q, w.x, a.x);
                a.y = fmaf(q, w.y, a.y);
                a.z = fmaf(q, w.z, a.z);
                a.w = fmaf(q, w.w, a.w);
            }
            a.x *= 0.25f; a.y *= 0.25f; a.z *= 0.25f; a.w *= 0.25f;
            *(float4*)&g_qk[(size_t)s * QKD + h * CKVv + c4 * 4] = a;
        }
        __syncwarp();   // Qs reads complete before next iter overwrites
    }
}

// ---------------------------------------------------------------------------
// scan_kernel (launch 1): exclusive scan of g_cnt; re-zeroes g_cnt.
// ---------------------------------------------------------------------------
__global__ void scan_kernel() {
    __shared__ int wsum[32];
    int t = threadIdx.x, lane = t & 31, wid = t >> 5;
    int4 c = ((const int4*)g_cnt)[t];
    int sum = c.x + c.y + c.z + c.w;
    int v = sum;
    #pragma unroll
    for (int o = 1; o < 32; o <<= 1) {
        int u = __shfl_up_sync(0xffffffffu, v, o);
        if (lane >= o) v += u;
    }
    if (lane == 31) wsum[wid] = v;
    __syncthreads();
    if (wid == 0) {
        int w = wsum[lane];
        #pragma unroll
        for (int o = 1; o < 32; o <<= 1) {
            int u = __shfl_up_sync(0xffffffffu, w, o);
            if (lane >= o) w += u;
        }
        wsum[lane] = w;
    }
    __syncthreads();
    int base = (wid ? wsum[wid - 1] : 0) + v - sum;
    int o0 = base, o1 = o0 + c.x, o2 = o1 + c.y, o3 = o2 + c.z;
    int4 ov = make_int4(o0, o1, o2, o3);
    ((int4*)g_offs)[t]   = ov;
    ((int4*)g_cursor)[t] = ov;
    ((int4*)g_cnt)[t]    = make_int4(0, 0, 0, 0);
    if (t == 1023) g_offs[Sv] = o3 + c.w;
}

// ---------------------------------------------------------------------------
// scatter_kernel (launch 2)
// ---------------------------------------------------------------------------
__global__ void scatter_kernel(const int* __restrict__ assign) {
    int tid = blockIdx.x * blockDim.x + threadIdx.x;
    if (tid < Nv) {
        int s = assign[tid];
        int pos = atomicAdd(&g_cursor[s], 1);
        g_order[pos] = tid;
    }
}

// ---------------------------------------------------------------------------
// seg_kernel (launch 3 — PROFILED): warp-autonomous core + FUSED Wv/LN tail.
// One block per segment, chunk = 128 points, padded-68 x tile.
// ---------------------------------------------------------------------------
__global__ void __launch_bounds__(128, 5)
seg_kernel(const float* __restrict__ xin, const float* __restrict__ sp,
           const float* __restrict__ lnw, const float* __restrict__ lnb,
           float* __restrict__ out, float* __restrict__ attn_out) {
    __shared__ float x_s[128 * XP];       // 34816 B; reused: reduction buf, then Wv
    __shared__ float qk_s[QKD];
    __shared__ float w_s[4 * Hv * 32];
    __shared__ float den_red[4 * Hv];
    __shared__ float A_s[Hv * CKVv];
    __shared__ float den_s[Hv];
    __shared__ float red_s[4];

    int s = blockIdx.x, t = threadIdx.x;
    int wi = t >> 5, lane = t & 31;
    int g = lane >> 4, c4 = lane & 15;

    ((float4*)qk_s)[t] = ((const float4*)(g_qk + (size_t)s * QKD))[t];

    int start = g_offs[s], end = g_offs[s + 1];
    float4 A0 = make_float4(0.f,0.f,0.f,0.f), A1 = A0, A2 = A0, A3 = A0;
    float d0 = 0.f, d1 = 0.f, d2 = 0.f, d3 = 0.f;
    __syncthreads();

    for (int base = start; base < end; base += 128) {
        int P = min(128, end - base);

        for (int idx = t; idx < P * 16; idx += 128) {
            int r = idx >> 4, cc = idx & 15;
            int p = g_order[base + r];
            float4 v = ((const float4*)xin)[(size_t)p * 16 + cc];
            *(float4*)&x_s[r * XP + (cc << 2)] = v;
        }
        __syncthreads();

        // ---- score phase (warp-local) ----
        int r = wi * 32 + lane;
        if (r < P) {
            const float* xrow = x_s + r * XP;
            float sc0=0.f,sc1=0.f,sc2=0.f,sc3=0.f,sc4=0.f,sc5=0.f,sc6=0.f,sc7=0.f;
            #pragma unroll
            for (int i = 0; i < 16; ++i) {
                float4 x = *(const float4*)&xrow[i << 2];
                float4 q;
                q = *(const float4*)&qk_s[0 * 64 + (i << 2)];
                sc0 = fmaf(q.x,x.x,sc0); sc0 = fmaf(q.y,x.y,sc0);
                sc0 = fmaf(q.z,x.z,sc0); sc0 = fmaf(q.w,x.w,sc0);
                q = *(const float4*)&qk_s[1 * 64 + (i << 2)];
                sc1 = fmaf(q.x,x.x,sc1); sc1 = fmaf(q.y,x.y,sc1);
                sc1 = fmaf(q.z,x.z,sc1); sc1 = fmaf(q.w,x.w,sc1);
                q = *(const float4*)&qk_s[2 * 64 + (i << 2)];
                sc2 = fmaf(q.x,x.x,sc2); sc2 = fmaf(q.y,x.y,sc2);
                sc2 = fmaf(q.z,x.z,sc2); sc2 = fmaf(q.w,x.w,sc2);
                q = *(const float4*)&qk_s[3 * 64 + (i << 2)];
                sc3 = fmaf(q.x,x.x,sc3); sc3 = fmaf(q.y,x.y,sc3);
                sc3 = fmaf(q.z,x.z,sc3); sc3 = fmaf(q.w,x.w,sc3);
                q = *(const float4*)&qk_s[4 * 64 + (i << 2)];
                sc4 = fmaf(q.x,x.x,sc4); sc4 = fmaf(q.y,x.y,sc4);
                sc4 = fmaf(q.z,x.z,sc4); sc4 = fmaf(q.w,x.w,sc4);
                q = *(const float4*)&qk_s[5 * 64 + (i << 2)];
                sc5 = fmaf(q.x,x.x,sc5); sc5 = fmaf(q.y,x.y,sc5);
                sc5 = fmaf(q.z,x.z,sc5); sc5 = fmaf(q.w,x.w,sc5);
                q = *(const float4*)&qk_s[6 * 64 + (i << 2)];
                sc6 = fmaf(q.x,x.x,sc6); sc6 = fmaf(q.y,x.y,sc6);
                sc6 = fmaf(q.z,x.z,sc6); sc6 = fmaf(q.w,x.w,sc6);
                q = *(const float4*)&qk_s[7 * 64 + (i << 2)];
                sc7 = fmaf(q.x,x.x,sc7); sc7 = fmaf(q.y,x.y,sc7);
                sc7 = fmaf(q.z,x.z,sc7); sc7 = fmaf(q.w,x.w,sc7);
            }
            float* wb = w_s + wi * (Hv * 32);
            wb[0 * 32 + lane] = __expf(sc0);
            wb[1 * 32 + lane] = __expf(sc1);
            wb[2 * 32 + lane] = __expf(sc2);
            wb[3 * 32 + lane] = __expf(sc3);
            wb[4 * 32 + lane] = __expf(sc4);
            wb[5 * 32 + lane] = __expf(sc5);
            wb[6 * 32 + lane] = __expf(sc6);
            wb[7 * 32 + lane] = __expf(sc7);
            float ssum = sc0+sc1+sc2+sc3+sc4+sc5+sc6+sc7;
            attn_out[g_order[base + r]] = ssum * 0.125f;
        }
        __syncwarp();

        // ---- update phase (warp-local) ----
        int r0 = wi * 32;
        int Pw = P - r0;
        if (Pw > 32) Pw = 32;
        if (Pw > 0) {
            const float* wb = w_s + wi * (Hv * 32);
            int Pm = Pw & ~3;
            for (int pb = 0; pb < Pm; pb += 4) {
                float4 x0 = *(const float4*)&x_s[(r0 + pb + 0) * XP + (c4 << 2)];
                float4 x1 = *(const float4*)&x_s[(r0 + pb + 1) * XP + (c4 << 2)];
                float4 x2 = *(const float4*)&x_s[(r0 + pb + 2) * XP + (c4 << 2)];
                float4 x3 = *(const float4*)&x_s[(r0 + pb + 3) * XP + (c4 << 2)];
                float4 w4;
                w4 = *(const float4*)&wb[(g + 0) * 32 + pb];
                A0.x = fmaf(w4.x,x0.x,A0.x); A0.y = fmaf(w4.x,x0.y,A0.y);
                A0.z = fmaf(w4.x,x0.z,A0.z); A0.w = fmaf(w4.x,x0.w,A0.w);
                A0.x = fmaf(w4.y,x1.x,A0.x); A0.y = fmaf(w4.y,x1.y,A0.y);
                A0.z = fmaf(w4.y,x1.z,A0.z); A0.w = fmaf(w4.y,x1.w,A0.w);
                A0.x = fmaf(w4.z,x2.x,A0.x); A0.y = fmaf(w4.z,x2.y,A0.y);
                A0.z = fmaf(w4.z,x2.z,A0.z); A0.w = fmaf(w4.z,x2.w,A0.w);
                A0.x = fmaf(w4.w,x3.x,A0.x); A0.y = fmaf(w4.w,x3.y,A0.y);
                A0.z = fmaf(w4.w,x3.z,A0.z); A0.w = fmaf(w4.w,x3.w,A0.w);
                d0 += w4.x + w4.y + w4.z + w4.w;
                w4 = *(const float4*)&wb[(g + 2) * 32 + pb];
                A1.x = fmaf(w4.x,x0.x,A1.x); A1.y = fmaf(w4.x,x0.y,A1.y);
                A1.z = fmaf(w4.x,x0.z,A1.z); A1.w = fmaf(w4.x,x0.w,A1.w);
                A1.x = fmaf(w4.y,x1.x,A1.x); A1.y = fmaf(w4.y,x1.y,A1.y);
                A1.z = fmaf(w4.y,x1.z,A1.z); A1.w = fmaf(w4.y,x1.w,A1.w);
                A1.x = fmaf(w4.z,x2.x,A1.x); A1.y = fmaf(w4.z,x2.y,A1.y);
                A1.z = fmaf(w4.z,x2.z,A1.z); A1.w = fmaf(w4.z,x2.w,A1.w);
                A1.x = fmaf(w4.w,x3.x,A1.x); A1.y = fmaf(w4.w,x3.y,A1.y);
                A1.z = fmaf(w4.w,x3.z,A1.z); A1.w = fmaf(w4.w,x3.w,A1.w);
                d1 += w4.x + w4.y + w4.z + w4.w;
                w4 = *(const float4*)&wb[(g + 4) * 32 + pb];
                A2.x = fmaf(w4.x,x0.x,A2.x); A2.y = fmaf(w4.x,x0.y,A2.y);
                A2.z = fmaf(w4.x,x0.z,A2.z); A2.w = fmaf(w4.x,x0.w,A2.w);
                A2.x = fmaf(w4.y,x1.x,A2.x); A2.y = fmaf(w4.y,x1.y,A2.y);
                A2.z = fmaf(w4.y,x1.z,A2.z); A2.w = fmaf(w4.y,x1.w,A2.w);
                A2.x = fmaf(w4.z,x2.x,A2.x); A2.y = fmaf(w4.z,x2.y,A2.y);
                A2.z = fmaf(w4.z,x2.z,A2.z); A2.w = fmaf(w4.z,x2.w,A2.w);
                A2.x = fmaf(w4.w,x3.x,A2.x); A2.y = fmaf(w4.w,x3.y,A2.y);
                A2.z = fmaf(w4.w,x3.z,A2.z); A2.w = fmaf(w4.w,x3.w,A2.w);
                d2 += w4.x + w4.y + w4.z + w4.w;
                w4 = *(const float4*)&wb[(g + 6) * 32 + pb];
                A3.x = fmaf(w4.x,x0.x,A3.x); A3.y = fmaf(w4.x,x0.y,A3.y);
                A3.z = fmaf(w4.x,x0.z,A3.z); A3.w = fmaf(w4.x,x0.w,A3.w);
                A3.x = fmaf(w4.y,x1.x,A3.x); A3.y = fmaf(w4.y,x1.y,A3.y);
                A3.z = fmaf(w4.y,x1.z,A3.z); A3.w = fmaf(w4.y,x1.w,A3.w);
                A3.x = fmaf(w4.z,x2.x,A3.x); A3.y = fmaf(w4.z,x2.y,A3.y);
                A3.z = fmaf(w4.z,x2.z,A3.z); A3.w = fmaf(w4.z,x2.w,A3.w);
                A3.x = fmaf(w4.w,x3.x,A3.x); A3.y = fmaf(w4.w,x3.y,A3.y);
                A3.z = fmaf(w4.w,x3.z,A3.z); A3.w = fmaf(w4.w,x3.w,A3.w);
                d3 += w4.x + w4.y + w4.z + w4.w;
            }
            for (int k = Pm; k < Pw; ++k) {
                float4 xv = *(const float4*)&x_s[(r0 + k) * XP + (c4 << 2)];
                float w0 = wb[(g + 0) * 32 + k];
                float w1 = wb[(g + 2) * 32 + k];
                float w2 = wb[(g + 4) * 32 + k];
                float w3 = wb[(g + 6) * 32 + k];
                A0.x = fmaf(w0,xv.x,A0.x); A0.y = fmaf(w0,xv.y,A0.y);
                A0.z = fmaf(w0,xv.z,A0.z); A0.w = fmaf(w0,xv.w,A0.w);
                A1.x = fmaf(w1,xv.x,A1.x); A1.y = fmaf(w1,xv.y,A1.y);
                A1.z = fmaf(w1,xv.z,A1.z); A1.w = fmaf(w1,xv.w,A1.w);
                A2.x = fmaf(w2,xv.x,A2.x); A2.y = fmaf(w2,xv.y,A2.y);
                A2.z = fmaf(w2,xv.z,A2.z); A2.w = fmaf(w2,xv.w,A2.w);
                A3.x = fmaf(w3,xv.x,A3.x); A3.y = fmaf(w3,xv.y,A3.y);
                A3.z = fmaf(w3,xv.z,A3.z); A3.w = fmaf(w3,xv.w,A3.w);
                d0 += w0; d1 += w1; d2 += w2; d3 += w3;
            }
        }
        __syncthreads();
    }

    // ---- 4-warp reduction (x_s reused as [4][8][64] buffer) ----
    {
        float* rb = x_s + wi * QKD;
        *(float4*)&rb[(g + 0) * 64 + c4 * 4] = A0;
        *(float4*)&rb[(g + 2) * 64 + c4 * 4] = A1;
        *(float4*)&rb[(g + 4) * 64 + c4 * 4] = A2;
        *(float4*)&rb[(g + 6) * 64 + c4 * 4] = A3;
        if (c4 == 0) {
            den_red[wi * Hv + g + 0] = d0;
            den_red[wi * Hv + g + 2] = d1;
            den_red[wi * Hv + g + 4] = d2;
            den_red[wi * Hv + g + 6] = d3;
        }
    }
    __syncthreads();

    {
        int h = t >> 4, c4t = t & 15;
        float4 a0 = *(const float4*)&x_s[0 * QKD + h * 64 + c4t * 4];
        float4 a1 = *(const float4*)&x_s[1 * QKD + h * 64 + c4t * 4];
        float4 a2 = *(const float4*)&x_s[2 * QKD + h * 64 + c4t * 4];
        float4 a3 = *(const float4*)&x_s[3 * QKD + h * 64 + c4t * 4];
        *(float4*)&A_s[h * CKVv + c4t * 4] =
            make_float4(a0.x + a1.x + a2.x + a3.x,
                        a0.y + a1.y + a2.y + a3.y,
                        a0.z + a1.z + a2.z + a3.z,
                        a0.w + a1.w + a2.w + a3.w);
        if (c4t == 0)
            den_s[h] = den_red[0 * Hv + h] + den_red[1 * Hv + h] +
                       den_red[2 * Hv + h] + den_red[3 * Hv + h];
    }
    __syncthreads();

    // ---- fused tail: stage Wv into x_s (overwrite), ctx + residual + LN ----
    for (int idx = t; idx < Ev * CKVv / 4; idx += 128) {
        int r = idx >> 4, cc = idx & 15;
        float4 v = ((const float4*)g_Wv)[idx];
        *(float4*)&x_s[r * XP + (cc << 2)] = v;
    }
    __syncthreads();

    {
        int h = t >> 4;
        const float* wr = x_s + (size_t)t * XP;
        const float* ah = A_s + h * CKVv;
        float acc = 0.f;
        #pragma unroll
        for (int i = 0; i < 16; ++i) {
            float4 w = *(const float4*)&wr[i << 2];
            const float* a = ah + (i << 2);
            acc = fmaf(w.x, a[0], acc);
            acc = fmaf(w.y, a[1], acc);
            acc = fmaf(w.z, a[2], acc);
            acc = fmaf(w.w, a[3], acc);
        }
        float dd  = den_s[h];
        float ctx = dd > 0.f ? acc / dd : 0.f;
        float xval = sp[(size_t)s * Ev + t] + ctx;

        float v = xval;
        #pragma unroll
        for (int o = 16; o; o >>= 1) v += __shfl_xor_sync(0xffffffffu, v, o);
        if (lane == 0) red_s[wi] = v;
        __syncthreads();
        float mu = (red_s[0] + red_s[1] + red_s[2] + red_s[3]) * (1.f / Ev);
        float dv = xval - mu;
        float sq = dv * dv;
        #pragma unroll
        for (int o = 16; o; o >>= 1) sq += __shfl_xor_sync(0xffffffffu, sq, o);
        __syncthreads();
        if (lane == 0) red_s[wi] = sq;
        __syncthreads();
        float rstd = rsqrtf((red_s[0] + red_s[1] + red_s[2] + red_s[3]) * (1.f / Ev) + 1e-5f);
        out[(size_t)s * Ev + t] = dv * rstd * lnw[t] + lnb[t];
    }
}

// ---------------------------------------------------------------------------
// Launch: 4 launches (pre, scan, scatter, seg). seg = idx 3 (profiled).
// ---------------------------------------------------------------------------
extern "C" void kernel_launch(void* const* d_in, const int* in_sizes, int n_in,
                              void* d_out, int out_size) {
    const float* sp     = (const float*)d_in[0];
    const float* xin    = (const float*)d_in[1];
    const int*   assign = (const int*)d_in[2];
    const float* Wq     = (const float*)d_in[3];
    const float* Wkv    = (const float*)d_in[4];
    const float* lnw    = (const float*)d_in[5];
    const float* lnb    = (const float*)d_in[6];
    float* out      = (float*)d_out;
    float* attn_out = out + (size_t)Sv * Ev;

    int pre_smem = (Ev * WQP + Ev * XP) * (int)sizeof(float);    // 102.4 KB dynamic
    cudaFuncSetAttribute(pre_kernel, cudaFuncAttributeMaxDynamicSharedMemorySize, pre_smem);
    pre_kernel<<<PREB, 256, pre_smem>>>(sp, Wq, Wkv, assign);

    scan_kernel<<<1, 1024>>>();
    scatter_kernel<<<Nv / 256, 256>>>(assign);
    seg_kernel<<<Sv, 128>>>(xin, sp, lnw, lnb, out, attn_out);
}

// round 16
// speedup vs baseline: 1.1607x; 1.0538x over previous
#include <cuda_runtime.h>

// Problem constants
#define Sv   4096
#define Nv   262144
#define Ev   128
#define Hv   8
#define Dv   16
#define CKVv 64
#define QKD  512      // Hv * CKVv
#define XP   68       // padded row stride (floats) for 64-wide rows -> conflict-free
#define WQP  132      // padded row stride for 128-wide rows (Wq)
#define PREB 296      // pre grid (2 blocks/SM)

// Device scratch (g_cnt invariant: zero at kernel_launch entry; scan re-zeroes)
__device__ __align__(16) float g_Wv[Ev * CKVv];   // folded V weights [128][64]
__device__ __align__(16) float g_qk[Sv * QKD];    // per-segment folded query [S][8][64]
__device__ __align__(16) float g_A[Sv * QKD];     // per-segment weighted x sums
__device__ __align__(16) float g_den[Sv * Hv];
__device__ __align__(16) int g_cnt[Sv];
__device__ __align__(16) int g_offs[Sv + 4];
__device__ __align__(16) int g_cursor[Sv];
__device__ int g_order[Nv];

// ---------------------------------------------------------------------------
// pre_kernel (launch 0): histogram + Q/qk precompute + Wv fold.
// 296 blocks x 8 warps; warps LOOP segments (no in-loop block barriers).
// ---------------------------------------------------------------------------
__global__ void __launch_bounds__(256, 2)
pre_kernel(const float* __restrict__ sp, const float* __restrict__ Wq,
           const float* __restrict__ Wkv, const int* __restrict__ assign) {
    extern __shared__ float dyn[];
    float* Wq_s = dyn;                     // [128][WQP]
    float* Wk_s = dyn + Ev * WQP;          // [128][XP] folded K
    __shared__ float strip[8][2 * Ev];     // per warp: sp row | Q

    int t = threadIdx.x, lane = t & 31, wid = t >> 5;

    // histogram (grid-stride over all points)
    for (int p = blockIdx.x * 256 + t; p < Nv; p += PREB * 256)
        atomicAdd(&g_cnt[assign[p]], 1);

    // stage Wq (padded)
    for (int idx = t; idx < Ev * Ev / 4; idx += 256) {
        int j = idx >> 5, i4 = idx & 31;
        float4 v = ((const float4*)Wq)[idx];
        *(float4*)&Wq_s[j * WQP + (i4 << 2)] = v;
    }
    // fold + stage Wk (concat-duplication: cols c and c+64 summed)
    for (int idx = t; idx < Ev * CKVv / 4; idx += 256) {
        int r = idx >> 4, c4 = idx & 15;
        float4 a = *(const float4*)&Wkv[(size_t)r * 128 + c4 * 4];
        float4 b = *(const float4*)&Wkv[(size_t)r * 128 + 64 + c4 * 4];
        *(float4*)&Wk_s[r * XP + (c4 << 2)] =
            make_float4(a.x + b.x, a.y + b.y, a.z + b.z, a.w + b.w);
    }
    // block 0: fold Wv to global
    if (blockIdx.x == 0) {
        for (int idx = t; idx < Ev * CKVv / 4; idx += 256) {
            int r = idx >> 4, c4 = idx & 15;
            float4 a = *(const float4*)&Wkv[(size_t)(128 + r) * 128 + c4 * 4];
            float4 b = *(const float4*)&Wkv[(size_t)(128 + r) * 128 + 64 + c4 * 4];
            ((float4*)g_Wv)[idx] = make_float4(a.x + b.x, a.y + b.y, a.z + b.z, a.w + b.w);
        }
    }
    __syncthreads();   // the only block barrier

    float* sps = strip[wid];
    float* Qs  = strip[wid] + Ev;
    int g = lane >> 4, c4 = lane & 15;

    for (int s = blockIdx.x * 8 + wid; s < Sv; s += PREB * 8) {
        ((float4*)sps)[lane] = ((const float4*)(sp + (size_t)s * Ev))[lane];
        __syncwarp();

        #pragma unroll
        for (int k = 0; k < 4; ++k) {
            int j = lane + 32 * k;
            const float* wr = Wq_s + (size_t)j * WQP;
            float acc = 0.f;
            #pragma unroll
            for (int i4 = 0; i4 < 32; ++i4) {
                float4 w = *(const float4*)&wr[i4 << 2];
                acc = fmaf(w.x, sps[i4 * 4 + 0], acc);
                acc = fmaf(w.y, sps[i4 * 4 + 1], acc);
                acc = fmaf(w.z, sps[i4 * 4 + 2], acc);
                acc = fmaf(w.w, sps[i4 * 4 + 3], acc);
            }
            Qs[j] = acc;
        }
        __syncwarp();

        #pragma unroll
        for (int hh = 0; hh < 4; ++hh) {
            int h = g + 2 * hh;
            float4 a = make_float4(0.f, 0.f, 0.f, 0.f);
            #pragma unroll
            for (int d = 0; d < Dv; ++d) {
                int r = h * Dv + d;
                float q = Qs[r];
                float4 w = *(const float4*)&Wk_s[r * XP + (c4 << 2)];
                a.x = fmaf(q, w.x, a.x);
                a.y = fmaf(q, w.y, a.y);
                a.z = fmaf(q, w.z, a.z);
                a.w = fmaf(q, w.w, a.w);
            }
            a.x *= 0.25f; a.y *= 0.25f; a.z *= 0.25f; a.w *= 0.25f;
            *(float4*)&g_qk[(size_t)s * QKD + h * CKVv + c4 * 4] = a;
        }
        __syncwarp();
    }
}

// ---------------------------------------------------------------------------
// scan_kernel (launch 1): exclusive scan of g_cnt; re-zeroes g_cnt.
// ---------------------------------------------------------------------------
__global__ void scan_kernel() {
    __shared__ int wsum[32];
    int t = threadIdx.x, lane = t & 31, wid = t >> 5;
    int4 c = ((const int4*)g_cnt)[t];
    int sum = c.x + c.y + c.z + c.w;
    int v = sum;
    #pragma unroll
    for (int o = 1; o < 32; o <<= 1) {
        int u = __shfl_up_sync(0xffffffffu, v, o);
        if (lane >= o) v += u;
    }
    if (lane == 31) wsum[wid] = v;
    __syncthreads();
    if (wid == 0) {
        int w = wsum[lane];
        #pragma unroll
        for (int o = 1; o < 32; o <<= 1) {
            int u = __shfl_up_sync(0xffffffffu, w, o);
            if (lane >= o) w += u;
        }
        wsum[lane] = w;
    }
    __syncthreads();
    int base = (wid ? wsum[wid - 1] : 0) + v - sum;
    int o0 = base, o1 = o0 + c.x, o2 = o1 + c.y, o3 = o2 + c.z;
    int4 ov = make_int4(o0, o1, o2, o3);
    ((int4*)g_offs)[t]   = ov;
    ((int4*)g_cursor)[t] = ov;
    ((int4*)g_cnt)[t]    = make_int4(0, 0, 0, 0);
    if (t == 1023) g_offs[Sv] = o3 + c.w;
}

// ---------------------------------------------------------------------------
// scatter_kernel (launch 2)
// ---------------------------------------------------------------------------
__global__ void scatter_kernel(const int* __restrict__ assign) {
    int tid = blockIdx.x * blockDim.x + threadIdx.x;
    if (tid < Nv) {
        int s = assign[tid];
        int pos = atomicAdd(&g_cursor[s], 1);
        g_order[pos] = tid;
    }
}

// ---------------------------------------------------------------------------
// seg_kernel (launch 3 — PROFILED): warp-autonomous, padded-68 x tile,
// UNFUSED (writes g_A/g_den; Wv/LN in separate ln_kernel). Proven 49.6 us.
// ---------------------------------------------------------------------------
__global__ void __launch_bounds__(128, 5)
seg_kernel(const float* __restrict__ xin, float* __restrict__ attn_out) {
    __shared__ float x_s[128 * XP];       // 34816 B; reused as reduction buffer
    __shared__ float qk_s[QKD];
    __shared__ float w_s[4 * Hv * 32];
    __shared__ float den_red[4 * Hv];

    int s = blockIdx.x, t = threadIdx.x;
    int wi = t >> 5, lane = t & 31;
    int g = lane >> 4, c4 = lane & 15;

    ((float4*)qk_s)[t] = ((const float4*)(g_qk + (size_t)s * QKD))[t];

    int start = g_offs[s], end = g_offs[s + 1];
    float4 A0 = make_float4(0.f,0.f,0.f,0.f), A1 = A0, A2 = A0, A3 = A0;
    float d0 = 0.f, d1 = 0.f, d2 = 0.f, d3 = 0.f;
    __syncthreads();

    for (int base = start; base < end; base += 128) {
        int P = min(128, end - base);

        for (int idx = t; idx < P * 16; idx += 128) {
            int r = idx >> 4, cc = idx & 15;
            int p = g_order[base + r];
            float4 v = ((const float4*)xin)[(size_t)p * 16 + cc];
            *(float4*)&x_s[r * XP + (cc << 2)] = v;
        }
        __syncthreads();

        // ---- score phase (warp-local) ----
        int r = wi * 32 + lane;
        if (r < P) {
            const float* xrow = x_s + r * XP;
            float sc0=0.f,sc1=0.f,sc2=0.f,sc3=0.f,sc4=0.f,sc5=0.f,sc6=0.f,sc7=0.f;
            #pragma unroll
            for (int i = 0; i < 16; ++i) {
                float4 x = *(const float4*)&xrow[i << 2];
                float4 q;
                q = *(const float4*)&qk_s[0 * 64 + (i << 2)];
                sc0 = fmaf(q.x,x.x,sc0); sc0 = fmaf(q.y,x.y,sc0);
                sc0 = fmaf(q.z,x.z,sc0); sc0 = fmaf(q.w,x.w,sc0);
                q = *(const float4*)&qk_s[1 * 64 + (i << 2)];
                sc1 = fmaf(q.x,x.x,sc1); sc1 = fmaf(q.y,x.y,sc1);
                sc1 = fmaf(q.z,x.z,sc1); sc1 = fmaf(q.w,x.w,sc1);
                q = *(const float4*)&qk_s[2 * 64 + (i << 2)];
                sc2 = fmaf(q.x,x.x,sc2); sc2 = fmaf(q.y,x.y,sc2);
                sc2 = fmaf(q.z,x.z,sc2); sc2 = fmaf(q.w,x.w,sc2);
                q = *(const float4*)&qk_s[3 * 64 + (i << 2)];
                sc3 = fmaf(q.x,x.x,sc3); sc3 = fmaf(q.y,x.y,sc3);
                sc3 = fmaf(q.z,x.z,sc3); sc3 = fmaf(q.w,x.w,sc3);
                q = *(const float4*)&qk_s[4 * 64 + (i << 2)];
                sc4 = fmaf(q.x,x.x,sc4); sc4 = fmaf(q.y,x.y,sc4);
                sc4 = fmaf(q.z,x.z,sc4); sc4 = fmaf(q.w,x.w,sc4);
                q = *(const float4*)&qk_s[5 * 64 + (i << 2)];
                sc5 = fmaf(q.x,x.x,sc5); sc5 = fmaf(q.y,x.y,sc5);
                sc5 = fmaf(q.z,x.z,sc5); sc5 = fmaf(q.w,x.w,sc5);
                q = *(const float4*)&qk_s[6 * 64 + (i << 2)];
                sc6 = fmaf(q.x,x.x,sc6); sc6 = fmaf(q.y,x.y,sc6);
                sc6 = fmaf(q.z,x.z,sc6); sc6 = fmaf(q.w,x.w,sc6);
                q = *(const float4*)&qk_s[7 * 64 + (i << 2)];
                sc7 = fmaf(q.x,x.x,sc7); sc7 = fmaf(q.y,x.y,sc7);
                sc7 = fmaf(q.z,x.z,sc7); sc7 = fmaf(q.w,x.w,sc7);
            }
            float* wb = w_s + wi * (Hv * 32);
            wb[0 * 32 + lane] = __expf(sc0);
            wb[1 * 32 + lane] = __expf(sc1);
            wb[2 * 32 + lane] = __expf(sc2);
            wb[3 * 32 + lane] = __expf(sc3);
            wb[4 * 32 + lane] = __expf(sc4);
            wb[5 * 32 + lane] = __expf(sc5);
            wb[6 * 32 + lane] = __expf(sc6);
            wb[7 * 32 + lane] = __expf(sc7);
            float ssum = sc0+sc1+sc2+sc3+sc4+sc5+sc6+sc7;
            attn_out[g_order[base + r]] = ssum * 0.125f;
        }
        __syncwarp();

        // ---- update phase (warp-local) ----
        int r0 = wi * 32;
        int Pw = P - r0;
        if (Pw > 32) Pw = 32;
        if (Pw > 0) {
            const float* wb = w_s + wi * (Hv * 32);
            int Pm = Pw & ~3;
            for (int pb = 0; pb < Pm; pb += 4) {
                float4 x0 = *(const float4*)&x_s[(r0 + pb + 0) * XP + (c4 << 2)];
                float4 x1 = *(const float4*)&x_s[(r0 + pb + 1) * XP + (c4 << 2)];
                float4 x2 = *(const float4*)&x_s[(r0 + pb + 2) * XP + (c4 << 2)];
                float4 x3 = *(const float4*)&x_s[(r0 + pb + 3) * XP + (c4 << 2)];
                float4 w4;
                w4 = *(const float4*)&wb[(g + 0) * 32 + pb];
                A0.x = fmaf(w4.x,x0.x,A0.x); A0.y = fmaf(w4.x,x0.y,A0.y);
                A0.z = fmaf(w4.x,x0.z,A0.z); A0.w = fmaf(w4.x,x0.w,A0.w);
                A0.x = fmaf(w4.y,x1.x,A0.x); A0.y = fmaf(w4.y,x1.y,A0.y);
                A0.z = fmaf(w4.y,x1.z,A0.z); A0.w = fmaf(w4.y,x1.w,A0.w);
                A0.x = fmaf(w4.z,x2.x,A0.x); A0.y = fmaf(w4.z,x2.y,A0.y);
                A0.z = fmaf(w4.z,x2.z,A0.z); A0.w = fmaf(w4.z,x2.w,A0.w);
                A0.x = fmaf(w4.w,x3.x,A0.x); A0.y = fmaf(w4.w,x3.y,A0.y);
                A0.z = fmaf(w4.w,x3.z,A0.z); A0.w = fmaf(w4.w,x3.w,A0.w);
                d0 += w4.x + w4.y + w4.z + w4.w;
                w4 = *(const float4*)&wb[(g + 2) * 32 + pb];
                A1.x = fmaf(w4.x,x0.x,A1.x); A1.y = fmaf(w4.x,x0.y,A1.y);
                A1.z = fmaf(w4.x,x0.z,A1.z); A1.w = fmaf(w4.x,x0.w,A1.w);
                A1.x = fmaf(w4.y,x1.x,A1.x); A1.y = fmaf(w4.y,x1.y,A1.y);
                A1.z = fmaf(w4.y,x1.z,A1.z); A1.w = fmaf(w4.y,x1.w,A1.w);
                A1.x = fmaf(w4.z,x2.x,A1.x); A1.y = fmaf(w4.z,x2.y,A1.y);
                A1.z = fmaf(w4.z,x2.z,A1.z); A1.w = fmaf(w4.z,x2.w,A1.w);
                A1.x = fmaf(w4.w,x3.x,A1.x); A1.y = fmaf(w4.w,x3.y,A1.y);
                A1.z = fmaf(w4.w,x3.z,A1.z); A1.w = fmaf(w4.w,x3.w,A1.w);
                d1 += w4.x + w4.y + w4.z + w4.w;
                w4 = *(const float4*)&wb[(g + 4) * 32 + pb];
                A2.x = fmaf(w4.x,x0.x,A2.x); A2.y = fmaf(w4.x,x0.y,A2.y);
                A2.z = fmaf(w4.x,x0.z,A2.z); A2.w = fmaf(w4.x,x0.w,A2.w);
                A2.x = fmaf(w4.y,x1.x,A2.x); A2.y = fmaf(w4.y,x1.y,A2.y);
                A2.z = fmaf(w4.y,x1.z,A2.z); A2.w = fmaf(w4.y,x1.w,A2.w);
                A2.x = fmaf(w4.z,x2.x,A2.x); A2.y = fmaf(w4.z,x2.y,A2.y);
                A2.z = fmaf(w4.z,x2.z,A2.z); A2.w = fmaf(w4.z,x2.w,A2.w);
                A2.x = fmaf(w4.w,x3.x,A2.x); A2.y = fmaf(w4.w,x3.y,A2.y);
                A2.z = fmaf(w4.w,x3.z,A2.z); A2.w = fmaf(w4.w,x3.w,A2.w);
                d2 += w4.x + w4.y + w4.z + w4.w;
                w4 = *(const float4*)&wb[(g + 6) * 32 + pb];
                A3.x = fmaf(w4.x,x0.x,A3.x); A3.y = fmaf(w4.x,x0.y,A3.y);
                A3.z = fmaf(w4.x,x0.z,A3.z); A3.w = fmaf(w4.x,x0.w,A3.w);
                A3.x = fmaf(w4.y,x1.x,A3.x); A3.y = fmaf(w4.y,x1.y,A3.y);
                A3.z = fmaf(w4.y,x1.z,A3.z); A3.w = fmaf(w4.y,x1.w,A3.w);
                A3.x = fmaf(w4.z,x2.x,A3.x); A3.y = fmaf(w4.z,x2.y,A3.y);
                A3.z = fmaf(w4.z,x2.z,A3.z); A3.w = fmaf(w4.z,x2.w,A3.w);
                A3.x = fmaf(w4.w,x3.x,A3.x); A3.y = fmaf(w4.w,x3.y,A3.y);
                A3.z = fmaf(w4.w,x3.z,A3.z); A3.w = fmaf(w4.w,x3.w,A3.w);
                d3 += w4.x + w4.y + w4.z + w4.w;
            }
            for (int k = Pm; k < Pw; ++k) {
                float4 xv = *(const float4*)&x_s[(r0 + k) * XP + (c4 << 2)];
                float w0 = wb[(g + 0) * 32 + k];
                float w1 = wb[(g + 2) * 32 + k];
                float w2 = wb[(g + 4) * 32 + k];
                float w3 = wb[(g + 6) * 32 + k];
                A0.x = fmaf(w0,xv.x,A0.x); A0.y = fmaf(w0,xv.y,A0.y);
                A0.z = fmaf(w0,xv.z,A0.z); A0.w = fmaf(w0,xv.w,A0.w);
                A1.x = fmaf(w1,xv.x,A1.x); A1.y = fmaf(w1,xv.y,A1.y);
                A1.z = fmaf(w1,xv.z,A1.z); A1.w = fmaf(w1,xv.w,A1.w);
                A2.x = fmaf(w2,xv.x,A2.x); A2.y = fmaf(w2,xv.y,A2.y);
                A2.z = fmaf(w2,xv.z,A2.z); A2.w = fmaf(w2,xv.w,A2.w);
                A3.x = fmaf(w3,xv.x,A3.x); A3.y = fmaf(w3,xv.y,A3.y);
                A3.z = fmaf(w3,xv.z,A3.z); A3.w = fmaf(w3,xv.w,A3.w);
                d0 += w0; d1 += w1; d2 += w2; d3 += w3;
            }
        }
        __syncthreads();
    }

    // ---- 4-warp reduction (x_s reused as [4][8][64] buffer) ----
    {
        float* rb = x_s + wi * QKD;
        *(float4*)&rb[(g + 0) * 64 + c4 * 4] = A0;
        *(float4*)&rb[(g + 2) * 64 + c4 * 4] = A1;
        *(float4*)&rb[(g + 4) * 64 + c4 * 4] = A2;
        *(float4*)&rb[(g + 6) * 64 + c4 * 4] = A3;
        if (c4 == 0) {
            den_red[wi * Hv + g + 0] = d0;
            den_red[wi * Hv + g + 2] = d1;
            den_red[wi * Hv + g + 4] = d2;
            den_red[wi * Hv + g + 6] = d3;
        }
    }
    __syncthreads();

    {
        int h = t >> 4, c4t = t & 15;
        float4 a0 = *(const float4*)&x_s[0 * QKD + h * 64 + c4t * 4];
        float4 a1 = *(const float4*)&x_s[1 * QKD + h * 64 + c4t * 4];
        float4 a2 = *(const float4*)&x_s[2 * QKD + h * 64 + c4t * 4];
        float4 a3 = *(const float4*)&x_s[3 * QKD + h * 64 + c4t * 4];
        float4 A = make_float4(a0.x + a1.x + a2.x + a3.x,
                               a0.y + a1.y + a2.y + a3.y,
                               a0.z + a1.z + a2.z + a3.z,
                               a0.w + a1.w + a2.w + a3.w);
        *(float4*)&g_A[(size_t)s * QKD + t * 4] = A;
        if (c4t == 0)
            g_den[s * Hv + h] = den_red[0 * Hv + h] + den_red[1 * Hv + h] +
                                den_red[2 * Hv + h] + den_red[3 * Hv + h];
    }
}

// ---------------------------------------------------------------------------
// ln_kernel (launch 4): WARP-PER-SEGMENT, padded Wv. Proven in R12.
// ---------------------------------------------------------------------------
__global__ void __launch_bounds__(256)
ln_kernel(const float* __restrict__ sp, const float* __restrict__ lnw,
          const float* __restrict__ lnb, float* __restrict__ out) {
    extern __shared__ float Wv_s[];        // [128][XP]
    __shared__ float A_strip[8][QKD];
    __shared__ float den_strip[8][Hv];

    int t = threadIdx.x, lane = t & 31, wid = t >> 5;

    for (int idx = t; idx < Ev * CKVv / 4; idx += 256) {
        int r = idx >> 4, cc = idx & 15;
        float4 v = ((const float4*)g_Wv)[idx];
        *(float4*)&Wv_s[r * XP + (cc << 2)] = v;
    }
    __syncthreads();   // the only block barrier

    int s = blockIdx.x * 8 + wid;
    float* As = A_strip[wid];
    float* ds = den_strip[wid];

    #pragma unroll
    for (int k = 0; k < 4; ++k)
        *(float4*)&As[(lane + 32 * k) * 4] = ((const float4*)(g_A + (size_t)s * QKD))[lane + 32 * k];
    if (lane < Hv) ds[lane] = g_den[s * Hv + lane];
    __syncwarp();

    float xval[4];
    #pragma unroll
    for (int k = 0; k < 4; ++k) {
        int e = lane + 32 * k;
        int h = e >> 4;
        const float* ah = As + h * CKVv;
        const float* wr = Wv_s + (size_t)e * XP;
        float acc = 0.f;
        #pragma unroll
        for (int i = 0; i < 16; ++i) {
            float4 w = *(const float4*)&wr[i << 2];
            const float* a = ah + (i << 2);
            acc = fmaf(w.x, a[0], acc);
            acc = fmaf(w.y, a[1], acc);
            acc = fmaf(w.z, a[2], acc);
            acc = fmaf(w.w, a[3], acc);
        }
        float dd = ds[h];
        float ctx = dd > 0.f ? acc / dd : 0.f;
        xval[k] = sp[(size_t)s * Ev + e] + ctx;
    }

    float ssum = xval[0] + xval[1] + xval[2] + xval[3];
    #pragma unroll
    for (int o = 16; o; o >>= 1) ssum += __shfl_xor_sync(0xffffffffu, ssum, o);
    float mu = ssum * (1.f / Ev);
    float sq = 0.f;
    #pragma unroll
    for (int k = 0; k < 4; ++k) {
        xval[k] -= mu;
        sq = fmaf(xval[k], xval[k], sq);
    }
    #pragma unroll
    for (int o = 16; o; o >>= 1) sq += __shfl_xor_sync(0xffffffffu, sq, o);
    float rstd = rsqrtf(sq * (1.f / Ev) + 1e-5f);
    #pragma unroll
    for (int k = 0; k < 4; ++k) {
        int e = lane + 32 * k;
        out[(size_t)s * Ev + e] = xval[k] * rstd * lnw[e] + lnb[e];
    }
}

// ---------------------------------------------------------------------------
// Launch: 5 launches (pre, scan, scatter, seg, ln). seg = idx 3 (profiled).
// ---------------------------------------------------------------------------
extern "C" void kernel_launch(void* const* d_in, const int* in_sizes, int n_in,
                              void* d_out, int out_size) {
    const float* sp     = (const float*)d_in[0];
    const float* xin    = (const float*)d_in[1];
    const int*   assign = (const int*)d_in[2];
    const float* Wq     = (const float*)d_in[3];
    const float* Wkv    = (const float*)d_in[4];
    const float* lnw    = (const float*)d_in[5];
    const float* lnb    = (const float*)d_in[6];
    float* out      = (float*)d_out;
    float* attn_out = out + (size_t)Sv * Ev;

    int pre_smem = (Ev * WQP + Ev * XP) * (int)sizeof(float);    // 102.4 KB dynamic
    cudaFuncSetAttribute(pre_kernel, cudaFuncAttributeMaxDynamicSharedMemorySize, pre_smem);
    pre_kernel<<<PREB, 256, pre_smem>>>(sp, Wq, Wkv, assign);

    scan_kernel<<<1, 1024>>>();
    scatter_kernel<<<Nv / 256, 256>>>(assign);
    seg_kernel<<<Sv, 128>>>(xin, attn_out);

    int ln_smem = Ev * XP * (int)sizeof(float);                  // 34.8 KB dynamic
    cudaFuncSetAttribute(ln_kernel, cudaFuncAttributeMaxDynamicSharedMemorySize, ln_smem);
    ln_kernel<<<512, 256, ln_smem>>>(sp, lnw, lnb, out);
}